// round 10
// baseline (speedup 1.0000x reference)
#include <cuda_runtime.h>
#include <cuda_bf16.h>
#include <mma.h>

using namespace nvcuda;

// Problem constants (fixed by setup_inputs)
#define NB    4
#define LQn   4096
#define CC    384
#define NHH   6
#define NPP   4
#define DHH   64
#define GRD   64           // HL = WL = 64
#define ROWS  (NB*LQn)     // 16384
#define PROJN 128          // 48 (offsets) + 24 (attn logits), padded

// ---------------- scratch (static device arrays; no runtime alloc) ----------
__device__ __nv_bfloat16 g_q[ROWS*CC];        // LN(query), bf16
__device__ __nv_bfloat16 g_f[ROWS*CC];        // LN(feat), bf16
__device__ __nv_bfloat16 g_value[ROWS*CC];    // f@Wv + bv, bf16 [B,LV,NH,DH]
__device__ __nv_bfloat16 g_attn[ROWS*CC];     // sampled attn, bf16
__device__ float         g_proj[ROWS*PROJN];  // q@[Wo|Wa] + [bo|ba], fp32
__device__ __nv_bfloat16 g_Wv[CC*CC];
__device__ __nv_bfloat16 g_Wout[CC*CC];
__device__ __nv_bfloat16 g_Wproj[CC*PROJN];
__device__ float         g_bproj[PROJN];

// ---------------- prep: LayerNorm (q + f) fused with weight conversion ------
// blocks [0, 2*ROWS): LN rows (128 threads each).
// blocks [2*ROWS, 2*ROWS + CVT_BLKS): weight pack. 1152*128 = 147456 threads
// == CC*CC, exact cover of Wv/Wout (CC*PROJN and PROJN are subsets).
#define CVT_BLKS 1152
__global__ void prep_kernel(const float* __restrict__ query,
                            const float* __restrict__ feat,
                            const float* __restrict__ qg, const float* __restrict__ qb,
                            const float* __restrict__ fg, const float* __restrict__ fb,
                            const float* __restrict__ Wv,
                            const float* __restrict__ Wo,
                            const float* __restrict__ Wa,
                            const float* __restrict__ Wout,
                            const float* __restrict__ bo,
                            const float* __restrict__ ba)
{
    int blk = blockIdx.x;
    int t   = threadIdx.x;

    if (blk >= 2*ROWS) {
        // ---- weight conversion path ----
        int i = (blk - 2*ROWS) * 128 + t;   // 0 .. 147455
        if (i < CC*CC) {
            g_Wv[i]   = __float2bfloat16(Wv[i]);
            g_Wout[i] = __float2bfloat16(Wout[i]);
        }
        if (i < CC*PROJN) {
            int r = i / PROJN, c = i % PROJN;
            float v = 0.f;
            if (c < 48)      v = Wo[r*48 + c];
            else if (c < 72) v = Wa[r*24 + (c-48)];
            g_Wproj[i] = __float2bfloat16(v);
        }
        if (i < PROJN) {
            float v = 0.f;
            if (i < 48)      v = bo[i];
            else if (i < 72) v = ba[i-48];
            g_bproj[i] = v;
        }
        return;
    }

    // ---- LayerNorm path ----
    bool isQ = blk < ROWS;
    int  r   = isQ ? blk : blk - ROWS;
    const float* src = isQ ? query : feat;
    const float* gg  = isQ ? qg : fg;
    const float* bb  = isQ ? qb : fb;
    __nv_bfloat16* dst = isQ ? g_q : g_f;

    float x[3];
#pragma unroll
    for (int i = 0; i < 3; i++) x[i] = src[(size_t)r*CC + t + i*128];
    float s  = x[0]+x[1]+x[2];
    float s2 = x[0]*x[0]+x[1]*x[1]+x[2]*x[2];
#pragma unroll
    for (int o = 16; o > 0; o >>= 1) {
        s  += __shfl_down_sync(0xffffffffu, s,  o);
        s2 += __shfl_down_sync(0xffffffffu, s2, o);
    }
    __shared__ float sh[8];
    __shared__ float mu_s, rs_s;
    int w = t >> 5;
    if ((t & 31) == 0) { sh[w] = s; sh[4+w] = s2; }
    __syncthreads();
    if (t == 0) {
        float ts  = sh[0]+sh[1]+sh[2]+sh[3];
        float ts2 = sh[4]+sh[5]+sh[6]+sh[7];
        float mu  = ts * (1.f/CC);
        float var = ts2 * (1.f/CC) - mu*mu;
        mu_s = mu;
        rs_s = rsqrtf(var + 1e-6f);
    }
    __syncthreads();
    float mu = mu_s, rs = rs_s;
#pragma unroll
    for (int i = 0; i < 3; i++) {
        int c = t + i*128;
        dst[(size_t)r*CC + c] = __float2bfloat16((x[i]-mu)*rs*gg[c] + bb[c]);
    }
}

// ---------------- shared GEMM core ------------------------------------------
// 128x64 tile, BK=32, 8 warps (4x2 of 32x32), double-buffered smem with
// padded leading dims (A:40, B:72) for conflict-free LDSM.
struct GemmSmem {
    // A: 2*128*40*2 = 20480 B ; B: 2*32*72*2 = 9216 B  (tile phase)
    // C stage: 128*68*4 = 34816 B                      (epilogue phase)
    __align__(16) unsigned char raw[36864];
};

template<int N>
__device__ __forceinline__
void gemm_tile(const __nv_bfloat16* __restrict__ A,
               const __nv_bfloat16* __restrict__ Bm,
               GemmSmem& sm, int bm, int bn, float* Cs)
{
    constexpr int BM = 128, BN = 64, BK = 32, K = CC;
    constexpr int NT  = K / BK;                   // 12
    constexpr int LDA = BK + 8;                   // 40 elems = 80B rows
    constexpr int LDB = BN + 8;                   // 72 elems = 144B rows

    __nv_bfloat16* As = (__nv_bfloat16*)sm.raw;              // [2][128*LDA]
    __nv_bfloat16* Bs = (__nv_bfloat16*)(sm.raw + 20480);    // [2][32*LDB]

    const int tid = threadIdx.x;              // 256 threads, 8 warps
    const int wid = tid >> 5;
    const int wr  = wid >> 1, wc = wid & 1;   // 4x2 warp grid, 32x32 each

    const int a_r0 = tid >> 2, a_c = (tid & 3) * 8;   // A: 2 rows (+64), 8 cols
    const int b_r  = tid >> 3, b_c = (tid & 7) * 8;   // B: 1 row, 8 cols

    wmma::fragment<wmma::accumulator,16,16,16,float> acc[2][2];
#pragma unroll
    for (int i = 0; i < 2; i++)
#pragma unroll
        for (int j = 0; j < 2; j++) wmma::fill_fragment(acc[i][j], 0.f);

    // prime buffer 0
    *(uint4*)(As + a_r0*LDA + a_c) =
        *(const uint4*)&A[(size_t)(bm + a_r0)*K + a_c];
    *(uint4*)(As + (a_r0+64)*LDA + a_c) =
        *(const uint4*)&A[(size_t)(bm + a_r0 + 64)*K + a_c];
    *(uint4*)(Bs + b_r*LDB + b_c) =
        *(const uint4*)&Bm[(size_t)b_r*N + bn + b_c];
    __syncthreads();

    int buf = 0;
    for (int kt = 0; kt < NT; kt++) {
        uint4 pa0, pa1, pb;
        if (kt + 1 < NT) {
            int k0n = (kt + 1) * BK;
            pa0 = *(const uint4*)&A[(size_t)(bm + a_r0)*K      + k0n + a_c];
            pa1 = *(const uint4*)&A[(size_t)(bm + a_r0 + 64)*K + k0n + a_c];
            pb  = *(const uint4*)&Bm[(size_t)(k0n + b_r)*N + bn + b_c];
        }

        const __nv_bfloat16* Ab = As + buf*(BM*LDA);
        const __nv_bfloat16* Bb = Bs + buf*(BK*LDB);
#pragma unroll
        for (int kk = 0; kk < BK; kk += 16) {
            wmma::fragment<wmma::matrix_a,16,16,16,__nv_bfloat16,wmma::row_major> af[2];
            wmma::fragment<wmma::matrix_b,16,16,16,__nv_bfloat16,wmma::row_major> bfr[2];
#pragma unroll
            for (int i = 0; i < 2; i++)
                wmma::load_matrix_sync(af[i], Ab + (wr*32 + i*16)*LDA + kk, LDA);
#pragma unroll
            for (int j = 0; j < 2; j++)
                wmma::load_matrix_sync(bfr[j], Bb + kk*LDB + wc*32 + j*16, LDB);
#pragma unroll
            for (int i = 0; i < 2; i++)
#pragma unroll
                for (int j = 0; j < 2; j++)
                    wmma::mma_sync(acc[i][j], af[i], bfr[j], acc[i][j]);
        }

        if (kt + 1 < NT) {
            int nb = buf ^ 1;
            *(uint4*)(As + nb*(BM*LDA) + a_r0*LDA + a_c)      = pa0;
            *(uint4*)(As + nb*(BM*LDA) + (a_r0+64)*LDA + a_c) = pa1;
            *(uint4*)(Bs + nb*(BK*LDB) + b_r*LDB + b_c)       = pb;
        }
        __syncthreads();
        buf ^= 1;
    }

    // stage accumulators through smem (reuses tile buffers; loop ended on sync)
#pragma unroll
    for (int i = 0; i < 2; i++)
#pragma unroll
        for (int j = 0; j < 2; j++)
            wmma::store_matrix_sync(Cs + (wr*32 + i*16)*68 + wc*32 + j*16,
                                    acc[i][j], 68, wmma::mem_row_major);
    __syncthreads();
}

// ---------------- fused value + proj GEMMs (independent, one launch) --------
// blockIdx.y in [0,8): y<6 -> value GEMM tile (N=384, bn=y*64),
//                      y>=6 -> proj GEMM tile (N=128, bn=(y-6)*64).
__global__ __launch_bounds__(256)
void gemm01_kernel(const float* __restrict__ bv)
{
    __shared__ GemmSmem sm;
    float* Cs = (float*)sm.raw;
    const int tid = threadIdx.x;
    const int bm  = blockIdx.x * 128;

    if (blockIdx.y < 6) {
        int bn = blockIdx.y * 64;
        gemm_tile<CC>(g_f, g_Wv, sm, bm, bn, Cs);
        for (int i = tid; i < 128*64; i += 256) {
            int r = i >> 6, c = i & 63;
            int n = bn + c;
            g_value[(size_t)(bm + r)*CC + n] = __float2bfloat16(Cs[r*68 + c] + bv[n]);
        }
    } else {
        int bn = (blockIdx.y - 6) * 64;
        gemm_tile<PROJN>(g_q, g_Wproj, sm, bm, bn, Cs);
        for (int i = tid; i < 128*64; i += 256) {
            int r = i >> 6, c = i & 63;
            int n = bn + c;
            if (n < 72)
                g_proj[(size_t)(bm + r)*PROJN + n] = Cs[r*68 + c] + g_bproj[n];
        }
    }
}

// ---------------- output GEMM + residual ------------------------------------
__global__ __launch_bounds__(256)
void gemm2_kernel(const float* __restrict__ bout,
                  const float* __restrict__ resid,
                  const float* __restrict__ gam,
                  float* __restrict__ outF)
{
    __shared__ GemmSmem sm;
    float* Cs = (float*)sm.raw;
    const int tid = threadIdx.x;
    const int bm  = blockIdx.x * 128, bn = blockIdx.y * 64;

    gemm_tile<CC>(g_attn, g_Wout, sm, bm, bn, Cs);
    for (int i = tid; i < 128*64; i += 256) {
        int r = i >> 6, c = i & 63;
        int n = bn + c;
        size_t o = (size_t)(bm + r)*CC + n;
        outF[o] = resid[o] + gam[n] * (Cs[r*68 + c] + bout[n]);
    }
}

// ---------------- deformable sampling --------------------------------------
// One block per (b,q), 192 threads = 6 warps, one warp per head.
// Fully warp-local: lanes 0..15 compute the 16 corner (index, weight) pairs
// (lane = p*4 + c), softmax over the 4 points via shfl_xor among point
// groups; the gather loop broadcasts each pair with shfl. No smem, no
// __syncthreads.
__global__ void sample_kernel(const float* __restrict__ refp)
{
    int row = blockIdx.x;
    int b   = row >> 12;            // row / 4096
    int t   = threadIdx.x;
    int h   = t >> 5;               // warp id = head
    int ln  = t & 31;

    const float* pr = g_proj + (size_t)row * PROJN;

    // lanes 0..15: one (point p, corner c) each
    int p = (ln >> 2) & 3;          // point
    int c = ln & 3;                 // corner

    // softmax weight for point p (p-groups of 4 lanes hold equal values;
    // shfl_xor 4/8 reduces across the 4 distinct points)
    float lg = pr[48 + h*NPP + p];
    float m = lg;
    m = fmaxf(m, __shfl_xor_sync(0xffffffffu, m, 4));
    m = fmaxf(m, __shfl_xor_sync(0xffffffffu, m, 8));
    float e = __expf(lg - m);
    float se = e;
    se += __shfl_xor_sync(0xffffffffu, se, 4);
    se += __shfl_xor_sync(0xffffffffu, se, 8);
    float aw = e / se;

    // sampling location for point p
    float x = refp[row*2 + 0] * (float)GRD - 0.5f + pr[h*8 + p*2 + 0];
    float y = refp[row*2 + 1] * (float)GRD - 0.5f + pr[h*8 + p*2 + 1];
    float fx = floorf(x), fy = floorf(y);
    float wx = x - fx,    wy = y - fy;
    int x0 = (int)fx + (c & 1);
    int y0 = (int)fy + (c >> 1);
    float cwx = (c & 1)  ? wx : 1.f - wx;
    float cwy = (c >> 1) ? wy : 1.f - wy;
    bool valid = (x0 >= 0) & (x0 < GRD) & (y0 >= 0) & (y0 < GRD);
    int xi = min(max(x0, 0), GRD-1);
    int yi = min(max(y0, 0), GRD-1);
    int   my_idx = yi * GRD + xi;
    float my_w   = valid ? cwx * cwy * aw : 0.f;

    // gather: each lane owns channel-pair ln; a warp load of one corner is a
    // full 128B line of that head's 64 channels
    const __nv_bfloat162* vb =
        (const __nv_bfloat162*)(g_value + (size_t)b * (LQn*CC) + h*DHH) + ln;
    float ax = 0.f, ay = 0.f;
#pragma unroll
    for (int i = 0; i < 16; i++) {
        int   idx = __shfl_sync(0xffffffffu, my_idx, i);
        float w   = __shfl_sync(0xffffffffu, my_w,   i);
        __nv_bfloat162 v = vb[(size_t)idx * (CC/2)];
        ax += w * __bfloat162float(v.x);
        ay += w * __bfloat162float(v.y);
    }
    ((__nv_bfloat162*)(g_attn + (size_t)row*CC + h*DHH))[ln] =
        __floats2bfloat162_rn(ax, ay);
}

// ---------------- launch -----------------------------------------------------
extern "C" void kernel_launch(void* const* d_in, const int* in_sizes, int n_in,
                              void* d_out, int out_size)
{
    const float* query  = (const float*)d_in[0];
    const float* refp   = (const float*)d_in[1];
    const float* feat   = (const float*)d_in[2];
    // d_in[3] spatial_shapes, d_in[4] level_start_index: constant [64,64],[0]
    const float* ln_q_g = (const float*)d_in[5];
    const float* ln_q_b = (const float*)d_in[6];
    const float* ln_f_g = (const float*)d_in[7];
    const float* ln_f_b = (const float*)d_in[8];
    const float* gamma  = (const float*)d_in[9];
    const float* Wv     = (const float*)d_in[10];
    const float* bv     = (const float*)d_in[11];
    const float* Wo     = (const float*)d_in[12];
    const float* bo     = (const float*)d_in[13];
    const float* Wa     = (const float*)d_in[14];
    const float* ba     = (const float*)d_in[15];
    const float* Wout   = (const float*)d_in[16];
    const float* bout   = (const float*)d_in[17];
    float* out = (float*)d_out;

    prep_kernel<<<2*ROWS + CVT_BLKS, 128>>>(query, feat, ln_q_g, ln_q_b,
                                            ln_f_g, ln_f_b,
                                            Wv, Wo, Wa, Wout, bo, ba);
    gemm01_kernel<<<dim3(ROWS/128, 8), 256>>>(bv);       // value + proj fused
    sample_kernel<<<ROWS, 192>>>(refp);
    gemm2_kernel<<<dim3(ROWS/128, CC/64), 256>>>(bout, query, gamma, out);
}